// round 9
// baseline (speedup 1.0000x reference)
#include <cuda_runtime.h>
#include <cuda_bf16.h>
#include <stdint.h>

#define NCODE 1024
#define CDIM  256
#define NPIX  65536
#define HW    1024
#define BCHW  16777216
#define FLAG_CAP 32768
#define CAND_CAP 131072
#define GAP_THRESH 6.0e-4f

// ---------------- device scratch (no allocations allowed) ----------------
__device__ __nv_bfloat16 g_xhi[(size_t)NPIX * CDIM];   // 32 MB
__device__ __nv_bfloat16 g_whi[NCODE * CDIM];
__device__ float g_wsq[NCODE];
__device__ float g_xsq[NPIX];
__device__ float g_bests[NPIX];
__device__ int   g_idx[NPIX];
__device__ unsigned long long g_key[NPIX];
__device__ int   g_flag_cnt;
__device__ int   g_flag_list[FLAG_CAP];
__device__ int   g_cand_cnt;
__device__ unsigned g_cand[CAND_CAP];

__device__ __forceinline__ uint32_t smem_u32(const void* p) {
    uint32_t a;
    asm("{ .reg .u64 t; cvta.to.shared.u64 t, %1; cvt.u32.u64 %0, t; }" : "=r"(a) : "l"(p));
    return a;
}

__device__ __forceinline__ unsigned long long packKey(float s, unsigned idx) {
    unsigned u = __float_as_uint(s);
    u = (u & 0x80000000u) ? ~u : (u | 0x80000000u);
    return (((unsigned long long)u) << 32) | (unsigned long long)idx;
}

__device__ __forceinline__ void cpasync16(uint32_t d, const void* s) {
    asm volatile("cp.async.ca.shared.global [%0], [%1], 16;" :: "r"(d), "l"(s) : "memory");
}

__device__ __forceinline__ void ldsm4(uint32_t* r, uint32_t addr) {
    asm volatile("ldmatrix.sync.aligned.m8n8.x4.shared.b16 {%0,%1,%2,%3}, [%4];"
                 : "=r"(r[0]), "=r"(r[1]), "=r"(r[2]), "=r"(r[3]) : "r"(addr));
}

__device__ __forceinline__ void mma_bf16(float* c, const uint32_t* a, const uint32_t* b) {
    asm volatile(
        "mma.sync.aligned.m16n8k16.row.col.f32.bf16.bf16.f32 "
        "{%0,%1,%2,%3}, {%4,%5,%6,%7}, {%8,%9}, {%0,%1,%2,%3};"
        : "+f"(c[0]), "+f"(c[1]), "+f"(c[2]), "+f"(c[3])
        : "r"(a[0]), "r"(a[1]), "r"(a[2]), "r"(a[3]), "r"(b[0]), "r"(b[1]));
}

// ---------------- prep kernels ----------------
__global__ void prep_w(const float* __restrict__ w) {
    __shared__ float red[8];
    int code = blockIdx.x, t = threadIdx.x;
    if (code == 0 && t == 0) { g_flag_cnt = 0; g_cand_cnt = 0; }
    float v = w[code * CDIM + t];
    g_whi[code * CDIM + t] = __float2bfloat16(v);
    float s = v * v;
    #pragma unroll
    for (int o = 16; o > 0; o >>= 1) s += __shfl_down_sync(0xffffffffu, s, o);
    if ((t & 31) == 0) red[t >> 5] = s;
    __syncthreads();
    if (t == 0) {
        g_wsq[code] = ((red[0] + red[1]) + (red[2] + red[3])) +
                      ((red[4] + red[5]) + (red[6] + red[7]));
    }
}

// x (B,C,H,W) f32 -> (pixel, C) bf16 + |x|^2
__global__ void prep_x(const float* __restrict__ x) {
    int p = blockIdx.x * 256 + threadIdx.x;
    const float* base = x + (size_t)(p >> 10) * (CDIM * HW) + (p & 1023);
    float s0 = 0.f, s1 = 0.f, s2 = 0.f, s3 = 0.f;
    uint4* dhi = (uint4*)(g_xhi + (size_t)p * CDIM);
    #pragma unroll 4
    for (int c = 0; c < CDIM; c += 8) {
        float v[8];
        #pragma unroll
        for (int i = 0; i < 8; i++) v[i] = base[(c + i) * HW];
        s0 += v[0] * v[0]; s1 += v[1] * v[1]; s2 += v[2] * v[2]; s3 += v[3] * v[3];
        s0 += v[4] * v[4]; s1 += v[5] * v[5]; s2 += v[6] * v[6]; s3 += v[7] * v[7];
        uint32_t hw_[4];
        #pragma unroll
        for (int i = 0; i < 4; i++) {
            __nv_bfloat16 h0 = __float2bfloat16(v[2 * i]);
            __nv_bfloat16 h1 = __float2bfloat16(v[2 * i + 1]);
            hw_[i] = (uint32_t)__bfloat16_as_ushort(h0) | ((uint32_t)__bfloat16_as_ushort(h1) << 16);
        }
        dhi[c >> 3] = make_uint4(hw_[0], hw_[1], hw_[2], hw_[3]);
    }
    g_xsq[p] = (s0 + s1) + (s2 + s3);
}

// Generic W-tile stager: 128 codes x 256 bf16 (64KB) at 'base', 256 threads
__device__ __forceinline__ void stage_wtile_at(uint32_t dstbase, int ct, int tid) {
    int r = tid >> 1, half = tid & 1;
    uint32_t dst = dstbase + (uint32_t)r * 512;
    uint32_t xm = (r & 7) << 4;
    const char* srow = (const char*)(g_whi + (size_t)(ct * 128 + r) * CDIM);
    #pragma unroll
    for (int j = 0; j < 16; j++) {
        uint32_t kb = half * 256 + j * 16;
        cpasync16(dst + (kb ^ xm), srow + kb);
    }
}

// 512-thread W-tile stager
__device__ __forceinline__ void stage_wtile512(uint32_t dstbase, int ct, int tid) {
    int r = tid >> 2, q = tid & 3;
    uint32_t dst = dstbase + (uint32_t)r * 512;
    uint32_t xm = (r & 7) << 4;
    const char* srow = (const char*)(g_whi + (size_t)(ct * 128 + r) * CDIM);
    #pragma unroll
    for (int j = 0; j < 8; j++) {
        uint32_t kb = q * 128 + j * 16;
        cpasync16(dst + (kb ^ xm), srow + kb);
    }
}

// ---------------- fused HMMA GEMM + top-2 argmin (64-px strips, 1024 CTAs) ----
#define VQ_SM_X   0
#define VQ_SM_W   32768
#define VQ_SM_RED 163840
#define VQ_SM_TOT (163840 + 3072)

__global__ __launch_bounds__(512, 1) void vq_mma() {
    extern __shared__ char smem[];
    uint32_t sb = smem_u32(smem);
    const int tid = threadIdx.x, l = tid & 31, wid = tid >> 5;
    const int mw = wid & 3;        // code-warp: 4 x 32 codes
    const int nw = wid >> 2;       // pixel-warp: 4 x 16 pixels
    const int row0 = blockIdx.x * 64;
    float* s1sh = (float*)(smem + VQ_SM_RED);
    int*   i1sh = (int*)(smem + VQ_SM_RED + 1024);
    float* s2sh = (float*)(smem + VQ_SM_RED + 2048);

    // Stage resident X strip: 64 rows x 512B, swizzled
    {
        int r = tid >> 3, o = tid & 7;
        const char* shi = (const char*)(g_xhi + (size_t)(row0 + r) * CDIM);
        uint32_t dx = sb + VQ_SM_X + (uint32_t)r * 512;
        uint32_t xm = (r & 7) << 4;
        #pragma unroll
        for (int j = 0; j < 4; j++) {
            uint32_t kb = o * 64 + j * 16;
            cpasync16(dx + (kb ^ xm), shi + kb);
        }
    }
    stage_wtile512(sb + VQ_SM_W, 0, tid);
    asm volatile("cp.async.commit_group;" ::: "memory");
    stage_wtile512(sb + VQ_SM_W + 65536, 1, tid);
    asm volatile("cp.async.commit_group;" ::: "memory");

    // 4 pixel slots per lane: px = nw*16 + (s>>1)*8 + (l&3)*2 + (s&1)
    float xsqr[4];
    #pragma unroll
    for (int s = 0; s < 4; s++) {
        int px = nw * 16 + (s >> 1) * 8 + (l & 3) * 2 + (s & 1);
        xsqr[s] = g_xsq[row0 + px];
    }

    uint32_t a_row[2], a_x[2];
    #pragma unroll
    for (int tm = 0; tm < 2; tm++) {
        int rA = mw * 32 + tm * 16 + (l & 15);
        a_row[tm] = rA * 512;
        a_x[tm] = (rA & 7) << 4;
    }
    const uint32_t off16a = (l >> 4) * 16;
    const int rB = nw * 16 + (l & 7) + ((l >> 4) << 3);
    const uint32_t b_row = rB * 512;
    const uint32_t b_x = (rB & 7) << 4;
    const uint32_t off16b = ((l >> 3) & 1) * 16;

    float acc[2][2][4];
    #pragma unroll
    for (int i = 0; i < 2; i++)
        #pragma unroll
        for (int j = 0; j < 2; j++)
            #pragma unroll
            for (int k = 0; k < 4; k++) acc[i][j][k] = 0.f;

    float best_s[4], sec_s[4];
    int best_i[4];
    #pragma unroll
    for (int s = 0; s < 4; s++) { best_s[s] = 3.4e38f; sec_s[s] = 3.4e38f; best_i[s] = 0; }

    for (int ct = 0; ct < 8; ct++) {
        if (ct < 7) asm volatile("cp.async.wait_group 1;" ::: "memory");
        else        asm volatile("cp.async.wait_group 0;" ::: "memory");
        __syncthreads();

        uint32_t bufw = sb + VQ_SM_W + (uint32_t)(ct & 1) * 65536;
        #pragma unroll 4
        for (int kk = 0; kk < 16; kk++) {
            uint32_t a0[4], a1[4], b[4];
            uint32_t ca = kk * 32 + off16a;
            ldsm4(a0, bufw + a_row[0] + (ca ^ a_x[0]));
            ldsm4(a1, bufw + a_row[1] + (ca ^ a_x[1]));
            ldsm4(b, sb + VQ_SM_X + b_row + ((kk * 32 + off16b) ^ b_x));
            mma_bf16(acc[0][0], a0, b);
            mma_bf16(acc[0][1], a0, b + 2);
            mma_bf16(acc[1][0], a1, b);
            mma_bf16(acc[1][1], a1, b + 2);
        }
        __syncthreads();   // all warps done reading bufw before restage
        if (ct + 2 < 8) {
            stage_wtile512(sb + VQ_SM_W + (uint32_t)(ct & 1) * 65536, ct + 2, tid);
            asm volatile("cp.async.commit_group;" ::: "memory");
        }

        // Fold this code tile into running top-2
        {
            int cb = ct * 128 + mw * 32 + (l >> 2);
            float wq0 = __ldg(&g_wsq[cb]);
            float wq1 = __ldg(&g_wsq[cb + 8]);
            float wq2 = __ldg(&g_wsq[cb + 16]);
            float wq3 = __ldg(&g_wsq[cb + 24]);
            #pragma unroll
            for (int tm = 0; tm < 2; tm++) {
                float wlo_ = tm ? wq2 : wq0;
                float whi_ = tm ? wq3 : wq1;
                int c_lo = cb + tm * 16, c_hi = cb + tm * 16 + 8;
                #pragma unroll
                for (int tn = 0; tn < 2; tn++) {
                    #pragma unroll
                    for (int rg = 0; rg < 4; rg++) {
                        int slot = tn * 2 + (rg & 1);
                        float dot = acc[tm][tn][rg];
                        float wq = (rg >> 1) ? whi_ : wlo_;
                        int code = (rg >> 1) ? c_hi : c_lo;
                        float s = __fadd_rn(__fsub_rn(xsqr[slot],
                                                      __fmul_rn(2.0f, dot)), wq);
                        if (s < best_s[slot]) {
                            sec_s[slot] = best_s[slot];
                            best_s[slot] = s; best_i[slot] = code;
                        } else if (s < sec_s[slot]) {
                            sec_s[slot] = s;
                        }
                        acc[tm][tn][rg] = 0.f;
                    }
                }
            }
        }
    }

    // Cross-lane top-2 merge (8 lanes share a pixel set)
    #pragma unroll
    for (int s = 0; s < 4; s++) {
        float bs = best_s[s], ss = sec_s[s];
        int bi = best_i[s];
        #pragma unroll
        for (int off = 4; off <= 16; off <<= 1) {
            float ob = __shfl_xor_sync(0xffffffffu, bs, off);
            int   oi = __shfl_xor_sync(0xffffffffu, bi, off);
            float os = __shfl_xor_sync(0xffffffffu, ss, off);
            bool take = (ob < bs) || (ob == bs && oi < bi);
            float losing = take ? bs : ob;
            if (take) { bs = ob; bi = oi; }
            ss = fminf(fminf(ss, os), losing);
        }
        if ((l >> 2) == 0) {
            int px = nw * 16 + (s >> 1) * 8 + (l & 3) * 2 + (s & 1);
            s1sh[mw * 64 + px] = bs;
            i1sh[mw * 64 + px] = bi;
            s2sh[mw * 64 + px] = ss;
        }
    }
    __syncthreads();

    // Cross-warp merge (4 code-warps per pixel); flag near-ties for rescue
    if (tid < 64) {
        float bs = s1sh[tid]; int bi = i1sh[tid]; float ss = s2sh[tid];
        #pragma unroll
        for (int wv = 1; wv < 4; wv++) {
            float ob = s1sh[wv * 64 + tid];
            int   oi = i1sh[wv * 64 + tid];
            float os = s2sh[wv * 64 + tid];
            bool take = (ob < bs) || (ob == bs && oi < bi);
            float losing = take ? bs : ob;
            if (take) { bs = ob; bi = oi; }
            ss = fminf(fminf(ss, os), losing);
        }
        int p = row0 + tid;
        g_bests[p] = bs;
        if (ss - bs < GAP_THRESH) {
            int slot = atomicAdd(&g_flag_cnt, 1);
            if (slot < FLAG_CAP) {
                g_flag_list[slot] = p;
                g_key[p] = ~0ull;
                g_idx[p] = -1;        // gather resolves from g_key
            } else {
                g_idx[p] = bi;
            }
        } else {
            g_idx[p] = bi;
        }
    }
}

// ---------------- rescue scan: approx-rescore flagged px, emit candidates ----
// smem: XS 64KB | W 64KB (single) | pxid 512B
#define SC_X   0
#define SC_W   65536
#define SC_PX  131072
#define SC_TOT (131072 + 512)

__global__ __launch_bounds__(256, 1) void rescue_scan() {
    extern __shared__ char smem[];
    uint32_t sb = smem_u32(smem);
    const int tid = threadIdx.x, l = tid & 31, wid = tid >> 5;
    const int mw = wid & 3, nw = wid >> 2;
    const int split = blockIdx.x & 7;        // code tile (one of 8)
    const int gslot = blockIdx.x >> 3;       // group slot (64)
    int* pxid = (int*)(smem + SC_PX);

    int nflag = g_flag_cnt;
    if (nflag > FLAG_CAP) nflag = FLAG_CAP;
    int ngroups = (nflag + 127) >> 7;
    if (gslot >= ngroups) return;

    stage_wtile_at(sb + SC_W, split, tid);
    asm volatile("cp.async.commit_group;" ::: "memory");

    uint32_t a_row[2], a_x[2];
    #pragma unroll
    for (int tm = 0; tm < 2; tm++) {
        int rA = mw * 32 + tm * 16 + (l & 15);
        a_row[tm] = rA * 512;
        a_x[tm] = (rA & 7) << 4;
    }
    const uint32_t off16a = (l >> 4) * 16;
    uint32_t b_row[4], b_x[4];
    #pragma unroll
    for (int tp = 0; tp < 4; tp++) {
        int rB = nw * 64 + tp * 16 + (l & 7) + ((l >> 4) << 3);
        b_row[tp] = rB * 512;
        b_x[tp] = (rB & 7) << 4;
    }
    const uint32_t off16b = ((l >> 3) & 1) * 16;

    float acc[2][8][4];
    #pragma unroll
    for (int i = 0; i < 2; i++)
        #pragma unroll
        for (int j = 0; j < 8; j++)
            #pragma unroll
            for (int k = 0; k < 4; k++) acc[i][j][k] = 0.f;

    for (int grp = gslot; grp < ngroups; grp += 64) {
        int base = grp * 128;
        __syncthreads();     // previous group done with XS
        if (tid < 128) {
            int fi = base + tid;
            pxid[tid] = g_flag_list[(fi < nflag) ? fi : (nflag - 1)];
        }
        __syncthreads();

        {
            int r = tid >> 1, half = tid & 1;
            const char* shi = (const char*)(g_xhi + (size_t)pxid[r] * CDIM);
            uint32_t dx = sb + SC_X + (uint32_t)r * 512;
            uint32_t xm = (r & 7) << 4;
            #pragma unroll
            for (int j = 0; j < 16; j++) {
                uint32_t kb = half * 256 + j * 16;
                cpasync16(dx + (kb ^ xm), shi + kb);
            }
        }
        asm volatile("cp.async.commit_group;" ::: "memory");

        float xsqr[16], lims[16];
        int pxs[16];
        #pragma unroll
        for (int s = 0; s < 16; s++) {
            int r = nw * 64 + (s >> 1) * 8 + (l & 3) * 2 + (s & 1);
            int p = pxid[r];
            pxs[s] = p;
            xsqr[s] = g_xsq[p];
            lims[s] = g_bests[p] + GAP_THRESH;
        }

        asm volatile("cp.async.wait_group 0;" ::: "memory");
        __syncthreads();

        uint32_t bufw = sb + SC_W;
        #pragma unroll 4
        for (int kk = 0; kk < 16; kk++) {
            uint32_t a0[4], a1[4];
            uint32_t ca = kk * 32 + off16a;
            ldsm4(a0, bufw + a_row[0] + (ca ^ a_x[0]));
            ldsm4(a1, bufw + a_row[1] + (ca ^ a_x[1]));
            uint32_t kb = kk * 32 + off16b;
            #pragma unroll
            for (int tp = 0; tp < 4; tp++) {
                uint32_t b[4];
                ldsm4(b, sb + SC_X + b_row[tp] + (kb ^ b_x[tp]));
                mma_bf16(acc[0][2 * tp],     a0, b);
                mma_bf16(acc[0][2 * tp + 1], a0, b + 2);
                mma_bf16(acc[1][2 * tp],     a1, b);
                mma_bf16(acc[1][2 * tp + 1], a1, b + 2);
            }
        }

        int cb = split * 128 + mw * 32 + (l >> 2);
        float wq0 = __ldg(&g_wsq[cb]);
        float wq1 = __ldg(&g_wsq[cb + 8]);
        float wq2 = __ldg(&g_wsq[cb + 16]);
        float wq3 = __ldg(&g_wsq[cb + 24]);
        #pragma unroll
        for (int tm = 0; tm < 2; tm++) {
            float wlo_ = tm ? wq2 : wq0;
            float whi_ = tm ? wq3 : wq1;
            int c_lo = cb + tm * 16, c_hi = cb + tm * 16 + 8;
            #pragma unroll
            for (int tn = 0; tn < 8; tn++) {
                #pragma unroll
                for (int rg = 0; rg < 4; rg++) {
                    int slot = tn * 2 + (rg & 1);
                    float dot = acc[tm][tn][rg];
                    float wq = (rg >> 1) ? whi_ : wlo_;
                    int code = (rg >> 1) ? c_hi : c_lo;
                    float s = __fadd_rn(__fsub_rn(xsqr[slot],
                                                  __fmul_rn(2.0f, dot)), wq);
                    if (s < lims[slot]) {
                        int ci = atomicAdd(&g_cand_cnt, 1);
                        if (ci < CAND_CAP)
                            g_cand[ci] = ((unsigned)pxs[slot] << 16) | (unsigned)code;
                    }
                    acc[tm][tn][rg] = 0.f;
                }
            }
        }
    }
}

// ---------------- exact fp32 scoring of candidates (1 warp each) ----------------
__global__ __launch_bounds__(256) void rescue_exact(const float* __restrict__ x,
                                                    const float* __restrict__ w) {
    const int l = threadIdx.x & 31, wid = threadIdx.x >> 5;
    int total = g_cand_cnt;
    if (total > CAND_CAP) total = CAND_CAP;
    for (int ci = blockIdx.x * 8 + wid; ci < total; ci += gridDim.x * 8) {
        unsigned pc = g_cand[ci];
        int px = pc >> 16, code = pc & 0xFFFF;
        const float* xb = x + (size_t)(px >> 10) * (CDIM * HW) + (px & 1023);
        const float* wr = w + (size_t)code * CDIM;
        float dot = 0.f;
        #pragma unroll
        for (int j = 0; j < 8; j++) {
            int c = l + j * 32;
            dot = fmaf(__ldg(&xb[(size_t)c * HW]), __ldg(&wr[c]), dot);
        }
        #pragma unroll
        for (int o = 16; o > 0; o >>= 1) dot += __shfl_down_sync(0xffffffffu, dot, o);
        if (l == 0) {
            float s = __fadd_rn(__fsub_rn(g_xsq[px], __fmul_rn(2.0f, dot)),
                                __ldg(&g_wsq[code]));
            atomicMin(&g_key[px], packKey(s, (unsigned)code));
        }
    }
}

// ---------------- gather + write outputs (resolves rescued pixels inline) ----
__global__ __launch_bounds__(256) void gather_kernel(const float* __restrict__ w,
                                                     float* __restrict__ out) {
    __shared__ float wsh[32][257];
    __shared__ int idxsh[32];

    const int bh = blockIdx.x;
    const int b  = bh >> 5;
    const int h  = bh & 31;
    const int p0 = bh * 32;
    const int tid = threadIdx.x;

    if (tid < 32) {
        int idx = g_idx[p0 + tid];
        if (idx < 0) idx = (int)(g_key[p0 + tid] & 0xFFFFFFFFULL);
        idxsh[tid] = idx;
        out[2 * BCHW + p0 + tid] = (float)idx;
    }
    __syncthreads();

    for (int j = tid; j < 32 * CDIM; j += 256) {
        int wl = j >> 8, c = j & 255;
        wsh[wl][c] = w[(size_t)idxsh[wl] * CDIM + c];
    }
    __syncthreads();

    const int qbase = b * (CDIM * HW) + h * 32;
    for (int j = tid; j < 32 * CDIM; j += 256) {
        int c = j >> 5, ww = j & 31;
        float v = wsh[ww][c];
        int addr = qbase + c * HW + ww;
        out[addr] = v;
        out[addr + BCHW] = v;
    }
}

extern "C" void kernel_launch(void* const* d_in, const int* in_sizes, int n_in,
                              void* d_out, int out_size) {
    const float* x = (const float*)d_in[0];   // (64, 256, 32, 32) f32
    const float* w = (const float*)d_in[1];   // (1024, 256) f32
    float* out = (float*)d_out;

    cudaFuncSetAttribute(vq_mma, cudaFuncAttributeMaxDynamicSharedMemorySize, VQ_SM_TOT);
    cudaFuncSetAttribute(rescue_scan, cudaFuncAttributeMaxDynamicSharedMemorySize, SC_TOT);

    prep_w<<<NCODE, 256>>>(w);
    prep_x<<<NPIX / 256, 256>>>(x);
    vq_mma<<<NPIX / 64, 512, VQ_SM_TOT>>>();
    rescue_scan<<<512, 256, SC_TOT>>>();
    rescue_exact<<<256, 256>>>(x, w);
    gather_kernel<<<NPIX / 32, 256>>>(w, out);
}

// round 10
// speedup vs baseline: 1.1551x; 1.1551x over previous
#include <cuda_runtime.h>
#include <cuda_fp16.h>
#include <stdint.h>

#define NCODE 1024
#define CDIM  256
#define NPIX  65536
#define HW    1024
#define BCHW  16777216
#define FLAG_CAP 32768
#define CAND_CAP 131072
#define GAP_THRESH 2.0e-4f

// ---------------- device scratch (no allocations allowed) ----------------
__device__ __half g_xhi[(size_t)NPIX * CDIM];   // 32 MB
__device__ __half g_whi[NCODE * CDIM];
__device__ float g_wsq[NCODE];
__device__ float g_xsq[NPIX];
__device__ float g_bests[NPIX];
__device__ int   g_idx[NPIX];
__device__ unsigned long long g_key[NPIX];
__device__ int   g_flag_cnt;
__device__ int   g_flag_list[FLAG_CAP];
__device__ int   g_cand_cnt;
__device__ unsigned g_cand[CAND_CAP];

__device__ __forceinline__ uint32_t smem_u32(const void* p) {
    uint32_t a;
    asm("{ .reg .u64 t; cvta.to.shared.u64 t, %1; cvt.u32.u64 %0, t; }" : "=r"(a) : "l"(p));
    return a;
}

__device__ __forceinline__ unsigned long long packKey(float s, unsigned idx) {
    unsigned u = __float_as_uint(s);
    u = (u & 0x80000000u) ? ~u : (u | 0x80000000u);
    return (((unsigned long long)u) << 32) | (unsigned long long)idx;
}

__device__ __forceinline__ void cpasync16(uint32_t d, const void* s) {
    asm volatile("cp.async.ca.shared.global [%0], [%1], 16;" :: "r"(d), "l"(s) : "memory");
}

__device__ __forceinline__ void ldsm4(uint32_t* r, uint32_t addr) {
    asm volatile("ldmatrix.sync.aligned.m8n8.x4.shared.b16 {%0,%1,%2,%3}, [%4];"
                 : "=r"(r[0]), "=r"(r[1]), "=r"(r[2]), "=r"(r[3]) : "r"(addr));
}

__device__ __forceinline__ void mma_f16(float* c, const uint32_t* a, const uint32_t* b) {
    asm volatile(
        "mma.sync.aligned.m16n8k16.row.col.f32.f16.f16.f32 "
        "{%0,%1,%2,%3}, {%4,%5,%6,%7}, {%8,%9}, {%0,%1,%2,%3};"
        : "+f"(c[0]), "+f"(c[1]), "+f"(c[2]), "+f"(c[3])
        : "r"(a[0]), "r"(a[1]), "r"(a[2]), "r"(a[3]), "r"(b[0]), "r"(b[1]));
}

// ---------------- prep kernels ----------------
__global__ void prep_w(const float* __restrict__ w) {
    __shared__ float red[8];
    int code = blockIdx.x, t = threadIdx.x;
    if (code == 0 && t == 0) { g_flag_cnt = 0; g_cand_cnt = 0; }
    float v = w[code * CDIM + t];
    g_whi[code * CDIM + t] = __float2half(v);
    float s = v * v;
    #pragma unroll
    for (int o = 16; o > 0; o >>= 1) s += __shfl_down_sync(0xffffffffu, s, o);
    if ((t & 31) == 0) red[t >> 5] = s;
    __syncthreads();
    if (t == 0) {
        g_wsq[code] = ((red[0] + red[1]) + (red[2] + red[3])) +
                      ((red[4] + red[5]) + (red[6] + red[7]));
    }
}

// x (B,C,H,W) f32 -> (pixel, C) fp16 + |x|^2
__global__ void prep_x(const float* __restrict__ x) {
    int p = blockIdx.x * 256 + threadIdx.x;
    const float* base = x + (size_t)(p >> 10) * (CDIM * HW) + (p & 1023);
    float s0 = 0.f, s1 = 0.f, s2 = 0.f, s3 = 0.f;
    uint4* dhi = (uint4*)(g_xhi + (size_t)p * CDIM);
    #pragma unroll 4
    for (int c = 0; c < CDIM; c += 8) {
        float v[8];
        #pragma unroll
        for (int i = 0; i < 8; i++) v[i] = base[(c + i) * HW];
        s0 += v[0] * v[0]; s1 += v[1] * v[1]; s2 += v[2] * v[2]; s3 += v[3] * v[3];
        s0 += v[4] * v[4]; s1 += v[5] * v[5]; s2 += v[6] * v[6]; s3 += v[7] * v[7];
        uint32_t hw_[4];
        #pragma unroll
        for (int i = 0; i < 4; i++) {
            __half2 h2 = __floats2half2_rn(v[2 * i], v[2 * i + 1]);
            hw_[i] = *(uint32_t*)&h2;
        }
        dhi[c >> 3] = make_uint4(hw_[0], hw_[1], hw_[2], hw_[3]);
    }
    g_xsq[p] = (s0 + s1) + (s2 + s3);
}

// Generic W-tile stager: 128 codes x 256 fp16 (64KB), 256 threads
__device__ __forceinline__ void stage_wtile_at(uint32_t dstbase, int ct, int tid) {
    int r = tid >> 1, half = tid & 1;
    uint32_t dst = dstbase + (uint32_t)r * 512;
    uint32_t xm = (r & 7) << 4;
    const char* srow = (const char*)(g_whi + (size_t)(ct * 128 + r) * CDIM);
    #pragma unroll
    for (int j = 0; j < 16; j++) {
        uint32_t kb = half * 256 + j * 16;
        cpasync16(dst + (kb ^ xm), srow + kb);
    }
}

// 512-thread W-tile stager
__device__ __forceinline__ void stage_wtile512(uint32_t dstbase, int ct, int tid) {
    int r = tid >> 2, q = tid & 3;
    uint32_t dst = dstbase + (uint32_t)r * 512;
    uint32_t xm = (r & 7) << 4;
    const char* srow = (const char*)(g_whi + (size_t)(ct * 128 + r) * CDIM);
    #pragma unroll
    for (int j = 0; j < 8; j++) {
        uint32_t kb = q * 128 + j * 16;
        cpasync16(dst + (kb ^ xm), srow + kb);
    }
}

// ---------------- fused HMMA GEMM + top-2 argmin (128-px strips, 512 CTAs) ----
#define SM_X   0
#define SM_W   65536
#define SM_RED 196608
#define SM_TOT (196608 + 6144)

__global__ __launch_bounds__(512, 1) void vq_mma() {
    extern __shared__ char smem[];
    uint32_t sb = smem_u32(smem);
    const int tid = threadIdx.x, l = tid & 31, wid = tid >> 5;
    const int mw = wid & 3;        // code-warp: 4 x 32 codes
    const int nw = wid >> 2;       // pixel-warp: 4 x 32 pixels
    const int row0 = blockIdx.x * 128;
    float* s1sh = (float*)(smem + SM_RED);
    int*   i1sh = (int*)(smem + SM_RED + 2048);
    float* s2sh = (float*)(smem + SM_RED + 4096);

    // Stage resident X strip (512B swizzled rows)
    {
        int r = tid >> 2, q = tid & 3;
        const char* shi = (const char*)(g_xhi + (size_t)(row0 + r) * CDIM);
        uint32_t dx = sb + SM_X + (uint32_t)r * 512;
        uint32_t xm = (r & 7) << 4;
        #pragma unroll
        for (int j = 0; j < 8; j++) {
            uint32_t kb = q * 128 + j * 16;
            cpasync16(dx + (kb ^ xm), shi + kb);
        }
    }
    stage_wtile512(sb + SM_W, 0, tid);
    asm volatile("cp.async.commit_group;" ::: "memory");
    stage_wtile512(sb + SM_W + 65536, 1, tid);
    asm volatile("cp.async.commit_group;" ::: "memory");

    float xsqr[8];
    #pragma unroll
    for (int s = 0; s < 8; s++) {
        int px = nw * 32 + (s >> 1) * 8 + (l & 3) * 2 + (s & 1);
        xsqr[s] = g_xsq[row0 + px];
    }

    uint32_t a_row[2], a_x[2];
    #pragma unroll
    for (int tm = 0; tm < 2; tm++) {
        int rA = mw * 32 + tm * 16 + (l & 15);
        a_row[tm] = rA * 512;
        a_x[tm] = (rA & 7) << 4;
    }
    const uint32_t off16a = (l >> 4) * 16;
    uint32_t b_row[2], b_x[2];
    #pragma unroll
    for (int tp = 0; tp < 2; tp++) {
        int rB = nw * 32 + tp * 16 + (l & 7) + ((l >> 4) << 3);
        b_row[tp] = rB * 512;
        b_x[tp] = (rB & 7) << 4;
    }
    const uint32_t off16b = ((l >> 3) & 1) * 16;

    float acc[2][4][4];
    #pragma unroll
    for (int i = 0; i < 2; i++)
        #pragma unroll
        for (int j = 0; j < 4; j++)
            #pragma unroll
            for (int k = 0; k < 4; k++) acc[i][j][k] = 0.f;

    float best_s[8], sec_s[8];
    int best_i[8];
    #pragma unroll
    for (int s = 0; s < 8; s++) { best_s[s] = 3.4e38f; sec_s[s] = 3.4e38f; best_i[s] = 0; }

    for (int ct = 0; ct < 8; ct++) {
        if (ct < 7) asm volatile("cp.async.wait_group 1;" ::: "memory");
        else        asm volatile("cp.async.wait_group 0;" ::: "memory");
        __syncthreads();

        uint32_t bufw = sb + SM_W + (uint32_t)(ct & 1) * 65536;
        #pragma unroll 4
        for (int kk = 0; kk < 16; kk++) {
            uint32_t a0[4], a1[4];
            uint32_t ca = kk * 32 + off16a;
            ldsm4(a0, bufw + a_row[0] + (ca ^ a_x[0]));
            ldsm4(a1, bufw + a_row[1] + (ca ^ a_x[1]));
            uint32_t kb = kk * 32 + off16b;
            #pragma unroll
            for (int tp = 0; tp < 2; tp++) {
                uint32_t b[4];
                ldsm4(b, sb + SM_X + b_row[tp] + (kb ^ b_x[tp]));
                mma_f16(acc[0][2 * tp],     a0, b);
                mma_f16(acc[0][2 * tp + 1], a0, b + 2);
                mma_f16(acc[1][2 * tp],     a1, b);
                mma_f16(acc[1][2 * tp + 1], a1, b + 2);
            }
        }
        __syncthreads();   // all warps done reading bufw before restage
        if (ct + 2 < 8) {
            stage_wtile512(sb + SM_W + (uint32_t)(ct & 1) * 65536, ct + 2, tid);
            asm volatile("cp.async.commit_group;" ::: "memory");
        }

        // Fold this code tile into running top-2
        {
            int cb = ct * 128 + mw * 32 + (l >> 2);
            float wq0 = __ldg(&g_wsq[cb]);
            float wq1 = __ldg(&g_wsq[cb + 8]);
            float wq2 = __ldg(&g_wsq[cb + 16]);
            float wq3 = __ldg(&g_wsq[cb + 24]);
            #pragma unroll
            for (int tm = 0; tm < 2; tm++) {
                float wlo_ = tm ? wq2 : wq0;
                float whi_ = tm ? wq3 : wq1;
                int c_lo = cb + tm * 16, c_hi = cb + tm * 16 + 8;
                #pragma unroll
                for (int tn = 0; tn < 4; tn++) {
                    #pragma unroll
                    for (int rg = 0; rg < 4; rg++) {
                        int slot = tn * 2 + (rg & 1);
                        float dot = acc[tm][tn][rg];
                        float wq = (rg >> 1) ? whi_ : wlo_;
                        int code = (rg >> 1) ? c_hi : c_lo;
                        float s = __fadd_rn(__fsub_rn(xsqr[slot],
                                                      __fmul_rn(2.0f, dot)), wq);
                        if (s < best_s[slot]) {
                            sec_s[slot] = best_s[slot];
                            best_s[slot] = s; best_i[slot] = code;
                        } else if (s < sec_s[slot]) {
                            sec_s[slot] = s;
                        }
                        acc[tm][tn][rg] = 0.f;
                    }
                }
            }
        }
    }

    // Cross-lane top-2 merge
    #pragma unroll
    for (int s = 0; s < 8; s++) {
        float bs = best_s[s], ss = sec_s[s];
        int bi = best_i[s];
        #pragma unroll
        for (int off = 4; off <= 16; off <<= 1) {
            float ob = __shfl_xor_sync(0xffffffffu, bs, off);
            int   oi = __shfl_xor_sync(0xffffffffu, bi, off);
            float os = __shfl_xor_sync(0xffffffffu, ss, off);
            bool take = (ob < bs) || (ob == bs && oi < bi);
            float losing = take ? bs : ob;
            if (take) { bs = ob; bi = oi; }
            ss = fminf(fminf(ss, os), losing);
        }
        if ((l >> 2) == 0) {
            int px = nw * 32 + (s >> 1) * 8 + (l & 3) * 2 + (s & 1);
            s1sh[mw * 128 + px] = bs;
            i1sh[mw * 128 + px] = bi;
            s2sh[mw * 128 + px] = ss;
        }
    }
    __syncthreads();

    // Cross-warp merge (4 code-warps per pixel); flag near-ties for rescue
    if (tid < 128) {
        float bs = s1sh[tid]; int bi = i1sh[tid]; float ss = s2sh[tid];
        #pragma unroll
        for (int wv = 1; wv < 4; wv++) {
            float ob = s1sh[wv * 128 + tid];
            int   oi = i1sh[wv * 128 + tid];
            float os = s2sh[wv * 128 + tid];
            bool take = (ob < bs) || (ob == bs && oi < bi);
            float losing = take ? bs : ob;
            if (take) { bs = ob; bi = oi; }
            ss = fminf(fminf(ss, os), losing);
        }
        int p = row0 + tid;
        g_bests[p] = bs;
        if (ss - bs < GAP_THRESH) {
            int slot = atomicAdd(&g_flag_cnt, 1);
            if (slot < FLAG_CAP) {
                g_flag_list[slot] = p;
                g_key[p] = ~0ull;
                g_idx[p] = -1;        // gather resolves from g_key
            } else {
                g_idx[p] = bi;
            }
        } else {
            g_idx[p] = bi;
        }
    }
}

// ---------------- rescue scan: approx-rescore flagged px, emit candidates ----
// smem: XS 64KB | W 64KB (single) | pxid 512B
#define SC_X   0
#define SC_W   65536
#define SC_PX  131072
#define SC_TOT (131072 + 512)

__global__ __launch_bounds__(256, 1) void rescue_scan() {
    extern __shared__ char smem[];
    uint32_t sb = smem_u32(smem);
    const int tid = threadIdx.x, l = tid & 31, wid = tid >> 5;
    const int mw = wid & 3, nw = wid >> 2;
    const int split = blockIdx.x & 7;        // code tile (one of 8)
    const int gslot = blockIdx.x >> 3;       // group slot (64)
    int* pxid = (int*)(smem + SC_PX);

    int nflag = g_flag_cnt;
    if (nflag > FLAG_CAP) nflag = FLAG_CAP;
    int ngroups = (nflag + 127) >> 7;
    if (gslot >= ngroups) return;

    stage_wtile_at(sb + SC_W, split, tid);
    asm volatile("cp.async.commit_group;" ::: "memory");

    uint32_t a_row[2], a_x[2];
    #pragma unroll
    for (int tm = 0; tm < 2; tm++) {
        int rA = mw * 32 + tm * 16 + (l & 15);
        a_row[tm] = rA * 512;
        a_x[tm] = (rA & 7) << 4;
    }
    const uint32_t off16a = (l >> 4) * 16;
    uint32_t b_row[4], b_x[4];
    #pragma unroll
    for (int tp = 0; tp < 4; tp++) {
        int rB = nw * 64 + tp * 16 + (l & 7) + ((l >> 4) << 3);
        b_row[tp] = rB * 512;
        b_x[tp] = (rB & 7) << 4;
    }
    const uint32_t off16b = ((l >> 3) & 1) * 16;

    float acc[2][8][4];
    #pragma unroll
    for (int i = 0; i < 2; i++)
        #pragma unroll
        for (int j = 0; j < 8; j++)
            #pragma unroll
            for (int k = 0; k < 4; k++) acc[i][j][k] = 0.f;

    for (int grp = gslot; grp < ngroups; grp += 64) {
        int base = grp * 128;
        __syncthreads();     // previous group done with XS
        if (tid < 128) {
            int fi = base + tid;
            pxid[tid] = g_flag_list[(fi < nflag) ? fi : (nflag - 1)];
        }
        __syncthreads();

        {
            int r = tid >> 1, half = tid & 1;
            const char* shi = (const char*)(g_xhi + (size_t)pxid[r] * CDIM);
            uint32_t dx = sb + SC_X + (uint32_t)r * 512;
            uint32_t xm = (r & 7) << 4;
            #pragma unroll
            for (int j = 0; j < 16; j++) {
                uint32_t kb = half * 256 + j * 16;
                cpasync16(dx + (kb ^ xm), shi + kb);
            }
        }
        asm volatile("cp.async.commit_group;" ::: "memory");

        float xsqr[16], lims[16];
        int pxs[16];
        #pragma unroll
        for (int s = 0; s < 16; s++) {
            int r = nw * 64 + (s >> 1) * 8 + (l & 3) * 2 + (s & 1);
            int p = pxid[r];
            pxs[s] = p;
            xsqr[s] = g_xsq[p];
            lims[s] = g_bests[p] + GAP_THRESH;
        }

        asm volatile("cp.async.wait_group 0;" ::: "memory");
        __syncthreads();

        uint32_t bufw = sb + SC_W;
        #pragma unroll 4
        for (int kk = 0; kk < 16; kk++) {
            uint32_t a0[4], a1[4];
            uint32_t ca = kk * 32 + off16a;
            ldsm4(a0, bufw + a_row[0] + (ca ^ a_x[0]));
            ldsm4(a1, bufw + a_row[1] + (ca ^ a_x[1]));
            uint32_t kb = kk * 32 + off16b;
            #pragma unroll
            for (int tp = 0; tp < 4; tp++) {
                uint32_t b[4];
                ldsm4(b, sb + SC_X + b_row[tp] + (kb ^ b_x[tp]));
                mma_f16(acc[0][2 * tp],     a0, b);
                mma_f16(acc[0][2 * tp + 1], a0, b + 2);
                mma_f16(acc[1][2 * tp],     a1, b);
                mma_f16(acc[1][2 * tp + 1], a1, b + 2);
            }
        }

        int cb = split * 128 + mw * 32 + (l >> 2);
        float wq0 = __ldg(&g_wsq[cb]);
        float wq1 = __ldg(&g_wsq[cb + 8]);
        float wq2 = __ldg(&g_wsq[cb + 16]);
        float wq3 = __ldg(&g_wsq[cb + 24]);
        #pragma unroll
        for (int tm = 0; tm < 2; tm++) {
            float wlo_ = tm ? wq2 : wq0;
            float whi_ = tm ? wq3 : wq1;
            int c_lo = cb + tm * 16, c_hi = cb + tm * 16 + 8;
            #pragma unroll
            for (int tn = 0; tn < 8; tn++) {
                #pragma unroll
                for (int rg = 0; rg < 4; rg++) {
                    int slot = tn * 2 + (rg & 1);
                    float dot = acc[tm][tn][rg];
                    float wq = (rg >> 1) ? whi_ : wlo_;
                    int code = (rg >> 1) ? c_hi : c_lo;
                    float s = __fadd_rn(__fsub_rn(xsqr[slot],
                                                  __fmul_rn(2.0f, dot)), wq);
                    if (s < lims[slot]) {
                        int ci = atomicAdd(&g_cand_cnt, 1);
                        if (ci < CAND_CAP)
                            g_cand[ci] = ((unsigned)pxs[slot] << 16) | (unsigned)code;
                    }
                    acc[tm][tn][rg] = 0.f;
                }
            }
        }
    }
}

// ---------------- exact fp32 scoring of candidates (1 warp each) ----------------
__global__ __launch_bounds__(256) void rescue_exact(const float* __restrict__ x,
                                                    const float* __restrict__ w) {
    const int l = threadIdx.x & 31, wid = threadIdx.x >> 5;
    int total = g_cand_cnt;
    if (total > CAND_CAP) total = CAND_CAP;
    for (int ci = blockIdx.x * 8 + wid; ci < total; ci += gridDim.x * 8) {
        unsigned pc = g_cand[ci];
        int px = pc >> 16, code = pc & 0xFFFF;
        const float* xb = x + (size_t)(px >> 10) * (CDIM * HW) + (px & 1023);
        const float* wr = w + (size_t)code * CDIM;
        float dot = 0.f;
        #pragma unroll
        for (int j = 0; j < 8; j++) {
            int c = l + j * 32;
            dot = fmaf(__ldg(&xb[(size_t)c * HW]), __ldg(&wr[c]), dot);
        }
        #pragma unroll
        for (int o = 16; o > 0; o >>= 1) dot += __shfl_down_sync(0xffffffffu, dot, o);
        if (l == 0) {
            float s = __fadd_rn(__fsub_rn(g_xsq[px], __fmul_rn(2.0f, dot)),
                                __ldg(&g_wsq[code]));
            atomicMin(&g_key[px], packKey(s, (unsigned)code));
        }
    }
}

// ---------------- gather + write outputs (resolves rescued pixels inline) ----
__global__ __launch_bounds__(256) void gather_kernel(const float* __restrict__ w,
                                                     float* __restrict__ out) {
    __shared__ float wsh[32][257];
    __shared__ int idxsh[32];

    const int bh = blockIdx.x;
    const int b  = bh >> 5;
    const int h  = bh & 31;
    const int p0 = bh * 32;
    const int tid = threadIdx.x;

    if (tid < 32) {
        int idx = g_idx[p0 + tid];
        if (idx < 0) idx = (int)(g_key[p0 + tid] & 0xFFFFFFFFULL);
        idxsh[tid] = idx;
        out[2 * BCHW + p0 + tid] = (float)idx;
    }
    __syncthreads();

    for (int j = tid; j < 32 * CDIM; j += 256) {
        int wl = j >> 8, c = j & 255;
        wsh[wl][c] = w[(size_t)idxsh[wl] * CDIM + c];
    }
    __syncthreads();

    const int qbase = b * (CDIM * HW) + h * 32;
    for (int j = tid; j < 32 * CDIM; j += 256) {
        int c = j >> 5, ww = j & 31;
        float v = wsh[ww][c];
        int addr = qbase + c * HW + ww;
        out[addr] = v;
        out[addr + BCHW] = v;
    }
}

extern "C" void kernel_launch(void* const* d_in, const int* in_sizes, int n_in,
                              void* d_out, int out_size) {
    const float* x = (const float*)d_in[0];   // (64, 256, 32, 32) f32
    const float* w = (const float*)d_in[1];   // (1024, 256) f32
    float* out = (float*)d_out;

    cudaFuncSetAttribute(vq_mma, cudaFuncAttributeMaxDynamicSharedMemorySize, SM_TOT);
    cudaFuncSetAttribute(rescue_scan, cudaFuncAttributeMaxDynamicSharedMemorySize, SC_TOT);

    prep_w<<<NCODE, 256>>>(w);
    prep_x<<<NPIX / 256, 256>>>(x);
    vq_mma<<<NPIX / 128, 512, SM_TOT>>>();
    rescue_scan<<<512, 256, SC_TOT>>>();
    rescue_exact<<<256, 256>>>(x, w);
    gather_kernel<<<NPIX / 32, 256>>>(w, out);
}